// round 8
// baseline (speedup 1.0000x reference)
#include <cuda_runtime.h>
#include <cstdint>

// ---------------------------------------------------------------------------
// EnsembleHead fused. B=1024, N=512, D_IN=30, H=64, 4H=256.
// R7: h broadcast via warp SHUFFLES (not broadcast LDS) -- crossbar was the
// bottleneck. RPB=8, 128 CTAs x 256 thr, 1 CTA/SM. xg hoisted to its own
// GEMM kernel (512MB scratch). prep parallelized (was 71us single-block).
// ---------------------------------------------------------------------------

typedef unsigned long long ull;

#define Bsz   1024
#define Nseq  512
#define DIN   30
#define RPB   8
#define NBLK  (Bsz / RPB)   // 128
#define MH    32            // h k-pairs
#define TTOK  64            // tokens per xg block
#define RSTRIDE (Nseq * 256)

// prep outputs + big intermediate
__device__ float g_wc[256 * DIN];      // W_comb[j][d]
__device__ float g_bc[256];            // b_comb
__device__ ull   g_whh_pk[MH * 256];   // [m][j] packed (w_2m, w_2m+1)
__device__ float g_xg[(size_t)Bsz * Nseq * 256];   // 512 MB scratch

// ---------------- helpers ----------------
__device__ __forceinline__ ull pkf2(float a, float b) {
    return (ull)__float_as_uint(a) | ((ull)__float_as_uint(b) << 32);
}
__device__ __forceinline__ ull ffma2(ull a, ull b, ull c) {
    ull d;
    asm("fma.rn.f32x2 %0, %1, %2, %3;" : "=l"(d) : "l"(a), "l"(b), "l"(c));
    return d;
}
__device__ __forceinline__ float sum2(ull v) {
    float lo, hi;
    asm("mov.b64 {%0, %1}, %2;" : "=f"(lo), "=f"(hi) : "l"(v));
    return lo + hi;
}
__device__ __forceinline__ float ex2a(float x) {
    float r; asm("ex2.approx.f32 %0, %1;" : "=f"(r) : "f"(x)); return r;
}
__device__ __forceinline__ float rcpa(float x) {
    float r; asm("rcp.approx.f32 %0, %1;" : "=f"(r) : "f"(x)); return r;
}
__device__ __forceinline__ float sigm(float x) {
    return rcpa(1.0f + ex2a(-1.4426950408889634f * x));
}
__device__ __forceinline__ float tanh_(float x) {
    return fmaf(2.0f, rcpa(1.0f + ex2a(-2.8853900817779268f * x)), -1.0f);
}

// ---------------------------------------------------------------------------
// prep (parallel): grid=256 (j), block=32. Butterfly-reduce over k.
// ---------------------------------------------------------------------------
__global__ void prep_kernel(const float* __restrict__ Wfc,
                            const float* __restrict__ bfc,
                            const float* __restrict__ Wih,
                            const float* __restrict__ Whh,
                            const float* __restrict__ bih,
                            const float* __restrict__ bhh)
{
    const int j = blockIdx.x;
    const int lane = threadIdx.x;

    const float w1 = Wih[j * 64 + lane];
    const float w2 = Wih[j * 64 + lane + 32];
    float acc[DIN];
#pragma unroll
    for (int d = 0; d < DIN; ++d)
        acc[d] = w1 * Wfc[lane * DIN + d] + w2 * Wfc[(lane + 32) * DIN + d];
    float bs = w1 * bfc[lane] + w2 * bfc[lane + 32];

#pragma unroll
    for (int off = 16; off >= 1; off >>= 1) {
#pragma unroll
        for (int d = 0; d < DIN; ++d)
            acc[d] += __shfl_xor_sync(0xffffffffu, acc[d], off);
        bs += __shfl_xor_sync(0xffffffffu, bs, off);
    }

    if (lane == 0) {
#pragma unroll
        for (int d = 0; d < DIN; ++d) g_wc[j * DIN + d] = acc[d];
        g_bc[j] = bs + bih[j] + bhh[j];
    }
    // whh pack: lane = m
    g_whh_pk[lane * 256 + j] = pkf2(Whh[j * 64 + 2 * lane],
                                    Whh[j * 64 + 2 * lane + 1]);
}

// ---------------------------------------------------------------------------
// xg_kernel: xg[tau][j] = sum_d Wc[j][d] * x[tau][d] + bc[j]
// block = 64 tokens; thread = gate-pair in f32x2 lanes for 32 tokens.
// ---------------------------------------------------------------------------
__global__ void __launch_bounds__(256, 2)
xg_kernel(const float* __restrict__ X)
{
    __shared__ __align__(16) float sx[TTOK * 64];
    const int tid = threadIdx.x;
    const int gp  = tid & 127;
    const int th  = tid >> 7;
    const size_t tau0 = (size_t)blockIdx.x * TTOK;

    const float* xf = X + tau0 * DIN;
    for (int i = tid; i < TTOK * DIN; i += 256) {
        float v = xf[i];
        int t = i / DIN, d = i - t * DIN;
        sx[t * 64 + 2 * d]     = v;
        sx[t * 64 + 2 * d + 1] = v;
    }

    ull wA[DIN];
#pragma unroll
    for (int d = 0; d < DIN; ++d)
        wA[d] = pkf2(g_wc[(2 * gp) * DIN + d], g_wc[(2 * gp + 1) * DIN + d]);
    const ull bias2 = pkf2(g_bc[2 * gp], g_bc[2 * gp + 1]);
    __syncthreads();

    float* outp = g_xg + (tau0 + (size_t)th * 32) * 256 + 2 * gp;
#pragma unroll 4
    for (int tt = 0; tt < 32; ++tt) {
        const ulonglong2* xv = (const ulonglong2*)(sx + (th * 32 + tt) * 64);
        ull acc = bias2;
#pragma unroll
        for (int qd = 0; qd < 15; ++qd) {
            ulonglong2 v = xv[qd];
            acc = ffma2(v.x, wA[2 * qd],     acc);
            acc = ffma2(v.y, wA[2 * qd + 1], acc);
        }
        *(ull*)(outp + (size_t)tt * 256) = acc;
    }
}

// ---------------------------------------------------------------------------
// lstm_kernel: RPB=8 rows/CTA, 1 CTA/SM. h broadcast via shfl64.
// shared layout (floats):
// ---------------------------------------------------------------------------
#define OFF_H    0      // 512  : h[r*64 + k]
#define OFF_G    512    // 2048 : gates[r*256 + j]
#define OFF_WL   2560   // 64
#define OFF_PART 2624   // 16   : [row*2 + khalf]
#define OFF_LOG  2640   // 4096 : logits [r][512]
#define SMEM_FLOATS 6736

__global__ void __launch_bounds__(256, 1)
lstm_kernel(const float* __restrict__ Wlast,
            const float* __restrict__ blast,
            float* __restrict__ out)
{
    __shared__ __align__(16) float s[SMEM_FLOATS];
    const int tid  = threadIdx.x;
    const int lane = tid & 31;
    const int wid  = tid >> 5;
    const int b0   = blockIdx.x * RPB;

    if (tid < 64) s[OFF_WL + tid] = Wlast[tid];
    s[OFF_H + tid] = 0.0f;
    s[OFF_H + 256 + tid] = 0.0f;

    // h-weights into registers (64 regs)
    ull wh[MH];
#pragma unroll
    for (int m = 0; m < MH; ++m) wh[m] = g_whh_pk[m * 256 + tid];
    const float blv = blast[0];

    // xg: thread j reads xg[(b0+r)*512 + t][j]
    const float* xgp = g_xg + (size_t)b0 * RSTRIDE + tid;
    float cur[RPB];
#pragma unroll
    for (int r = 0; r < RPB; ++r) cur[r] = xgp[(size_t)r * RSTRIDE];

    // update role: thread = (rp = tid>>6 in 0..3, k = tid&63), rows rp, rp+4
    const int rp = tid >> 6, uk = tid & 63;
    const int kh = wid & 1;               // k-half of this warp
    const int q  = tid >> 6;              // gate quarter (warp-uniform)
    __syncthreads();
    const float wlk = s[OFF_WL + uk];
    float cc0 = 0.0f, cc1 = 0.0f;

    for (int t = 0; t < Nseq; ++t) {
        // prefetch xg(t+1)
        float nf[RPB];
        if (t + 1 < Nseq) {
            const float* p = xgp + (size_t)(t + 1) * 256;
#pragma unroll
            for (int r = 0; r < RPB; ++r) nf[r] = p[(size_t)r * RSTRIDE];
        } else {
#pragma unroll
            for (int r = 0; r < RPB; ++r) nf[r] = 0.0f;
        }

        // pull h pairs: lane holds kp=lane for all 8 rows (conflict-free LDS.64)
        ull hp[RPB];
#pragma unroll
        for (int r = 0; r < RPB; ++r)
            hp[r] = *(const ull*)&s[OFF_H + r * 64 + 2 * lane];

        // ---- h-matvec via shuffle broadcast ----
        ull acc[RPB];
#pragma unroll
        for (int r = 0; r < RPB; ++r) acc[r] = pkf2(cur[r], 0.0f);

#pragma unroll
        for (int kp = 0; kp < MH; ++kp) {
            const ull w = wh[kp];
#pragma unroll
            for (int r = 0; r < RPB; ++r) {
                ull hv = __shfl_sync(0xffffffffu, hp[r], kp);
                acc[r] = ffma2(hv, w, acc[r]);
            }
        }

        // ---- activation (warp-uniform branch), store gates [r][j] ----
        if (q == 2) {
#pragma unroll
            for (int r = 0; r < RPB; ++r)
                s[OFF_G + r * 256 + tid] = tanh_(sum2(acc[r]));
        } else {
#pragma unroll
            for (int r = 0; r < RPB; ++r)
                s[OFF_G + r * 256 + tid] = sigm(sum2(acc[r]));
        }

        __syncthreads();   // gates ready

        // combine previous step's logit partials (8 threads, off hot path)
        if (t > 0 && tid < RPB)
            s[OFF_LOG + tid * Nseq + (t - 1)] =
                s[OFF_PART + 2 * tid] + s[OFF_PART + 2 * tid + 1] + blv;

        // ---- cell update: rows rp and rp+4 ----
        float gi0 = s[OFF_G + rp * 256 + uk];
        float gf0 = s[OFF_G + rp * 256 + uk + 64];
        float gg0 = s[OFF_G + rp * 256 + uk + 128];
        float go0 = s[OFF_G + rp * 256 + uk + 192];
        float gi1 = s[OFF_G + (rp + 4) * 256 + uk];
        float gf1 = s[OFF_G + (rp + 4) * 256 + uk + 64];
        float gg1 = s[OFF_G + (rp + 4) * 256 + uk + 128];
        float go1 = s[OFF_G + (rp + 4) * 256 + uk + 192];
        cc0 = fmaf(gf0, cc0, gi0 * gg0);
        cc1 = fmaf(gf1, cc1, gi1 * gg1);
        float hv0 = go0 * tanh_(cc0);
        float hv1 = go1 * tanh_(cc1);
        s[OFF_H + rp * 64 + uk]       = hv0;
        s[OFF_H + (rp + 4) * 64 + uk] = hv1;

        __syncthreads();   // h ready

        // logit partials -- after bar2, overlaps next step's prefetch/matvec
        float p0 = hv0 * wlk;
        float p1 = hv1 * wlk;
#pragma unroll
        for (int off = 16; off >= 1; off >>= 1) {
            p0 += __shfl_down_sync(0xffffffffu, p0, off);
            p1 += __shfl_down_sync(0xffffffffu, p1, off);
        }
        if (lane == 0) {
            s[OFF_PART + rp * 2 + kh]       = p0;
            s[OFF_PART + (rp + 4) * 2 + kh] = p1;
        }

#pragma unroll
        for (int r = 0; r < RPB; ++r) cur[r] = nf[r];
    }

    __syncthreads();
    if (tid < RPB)
        s[OFF_LOG + tid * Nseq + (Nseq - 1)] =
            s[OFF_PART + 2 * tid] + s[OFF_PART + 2 * tid + 1] + blv;
    __syncthreads();

    // ---- softmax over t: warp r handles row r (8 warps = 8 rows) ----
    {
        float v[16];
#pragma unroll
        for (int i = 0; i < 16; ++i)
            v[i] = s[OFF_LOG + wid * Nseq + i * 32 + lane];
        float m = v[0];
#pragma unroll
        for (int i = 1; i < 16; ++i) m = fmaxf(m, v[i]);
#pragma unroll
        for (int off = 16; off >= 1; off >>= 1)
            m = fmaxf(m, __shfl_xor_sync(0xffffffffu, m, off));

        float e[16], sum = 0.0f;
#pragma unroll
        for (int i = 0; i < 16; ++i) {
            e[i] = ex2a((v[i] - m) * 1.4426950408889634f);
            sum += e[i];
        }
#pragma unroll
        for (int off = 16; off >= 1; off >>= 1)
            sum += __shfl_xor_sync(0xffffffffu, sum, off);
        const float inv = 1.0f / sum;

        float* orow = out + (size_t)(b0 + wid) * Nseq;
#pragma unroll
        for (int i = 0; i < 16; ++i)
            orow[i * 32 + lane] = e[i] * inv;
    }
}

// ---------------------------------------------------------------------------
extern "C" void kernel_launch(void* const* d_in, const int* in_sizes, int n_in,
                              void* d_out, int out_size) {
    const float* x     = (const float*)d_in[0];
    const float* Wfc   = (const float*)d_in[1];
    const float* bfc   = (const float*)d_in[2];
    const float* Wih   = (const float*)d_in[3];
    const float* Whh   = (const float*)d_in[4];
    const float* bih   = (const float*)d_in[5];
    const float* bhh   = (const float*)d_in[6];
    const float* Wlast = (const float*)d_in[7];
    const float* blast = (const float*)d_in[8];
    float* out = (float*)d_out;

    prep_kernel<<<256, 32>>>(Wfc, bfc, Wih, Whh, bih, bhh);
    xg_kernel<<<(Bsz * Nseq) / TTOK, 256>>>(x);
    lstm_kernel<<<NBLK, 256>>>(Wlast, blast, out);
}

// round 9
// speedup vs baseline: 1.5815x; 1.5815x over previous
#include <cuda_runtime.h>
#include <cstdint>

// ---------------------------------------------------------------------------
// EnsembleHead fused. B=1024, N=512, D_IN=30, H=64, 4H=256.
// R8: lstm = 128 CTAs x 512 thr (1/SM), RPB=8. Thread (gate j, k-half ss):
// 16 weight u64 in regs, broadcast LDS.128 operands (warp-uniform addr),
// partial k-halves combined via one float4 smem exchange (3 barriers/step).
// xg (input-side GEMM) hoisted to its own kernel; prep parallel.
// ---------------------------------------------------------------------------

typedef unsigned long long ull;

#define Bsz   1024
#define Nseq  512
#define DIN   30
#define RPB   8
#define NBLK  (Bsz / RPB)   // 128
#define NTH   512
#define MH    32            // h k-pairs total
#define TTOK  64            // tokens per xg block
#define RSTRIDE (Nseq * 256)

// prep outputs + big intermediate
__device__ float g_wc[256 * DIN];      // W_comb[j][d]
__device__ float g_bc[256];            // b_comb
__device__ ull   g_whh_pk[MH * 256];   // [m][j] packed (w_2m, w_2m+1)
__device__ float g_xg[(size_t)Bsz * Nseq * 256];   // 512 MB scratch

// ---------------- helpers ----------------
__device__ __forceinline__ ull pkf2(float a, float b) {
    return (ull)__float_as_uint(a) | ((ull)__float_as_uint(b) << 32);
}
__device__ __forceinline__ ull ffma2(ull a, ull b, ull c) {
    ull d;
    asm("fma.rn.f32x2 %0, %1, %2, %3;" : "=l"(d) : "l"(a), "l"(b), "l"(c));
    return d;
}
__device__ __forceinline__ float sum2(ull v) {
    float lo, hi;
    asm("mov.b64 {%0, %1}, %2;" : "=f"(lo), "=f"(hi) : "l"(v));
    return lo + hi;
}
__device__ __forceinline__ float ex2a(float x) {
    float r; asm("ex2.approx.f32 %0, %1;" : "=f"(r) : "f"(x)); return r;
}
__device__ __forceinline__ float rcpa(float x) {
    float r; asm("rcp.approx.f32 %0, %1;" : "=f"(r) : "f"(x)); return r;
}
__device__ __forceinline__ float sigm(float x) {
    return rcpa(1.0f + ex2a(-1.4426950408889634f * x));
}
__device__ __forceinline__ float tanh_(float x) {
    return fmaf(2.0f, rcpa(1.0f + ex2a(-2.8853900817779268f * x)), -1.0f);
}

// ---------------------------------------------------------------------------
// prep (parallel): grid=256 (j), block=32. Butterfly-reduce over k.
// ---------------------------------------------------------------------------
__global__ void prep_kernel(const float* __restrict__ Wfc,
                            const float* __restrict__ bfc,
                            const float* __restrict__ Wih,
                            const float* __restrict__ Whh,
                            const float* __restrict__ bih,
                            const float* __restrict__ bhh)
{
    const int j = blockIdx.x;
    const int lane = threadIdx.x;

    const float w1 = Wih[j * 64 + lane];
    const float w2 = Wih[j * 64 + lane + 32];
    float acc[DIN];
#pragma unroll
    for (int d = 0; d < DIN; ++d)
        acc[d] = w1 * Wfc[lane * DIN + d] + w2 * Wfc[(lane + 32) * DIN + d];
    float bs = w1 * bfc[lane] + w2 * bfc[lane + 32];

#pragma unroll
    for (int off = 16; off >= 1; off >>= 1) {
#pragma unroll
        for (int d = 0; d < DIN; ++d)
            acc[d] += __shfl_xor_sync(0xffffffffu, acc[d], off);
        bs += __shfl_xor_sync(0xffffffffu, bs, off);
    }

    if (lane == 0) {
#pragma unroll
        for (int d = 0; d < DIN; ++d) g_wc[j * DIN + d] = acc[d];
        g_bc[j] = bs + bih[j] + bhh[j];
    }
    g_whh_pk[lane * 256 + j] = pkf2(Whh[j * 64 + 2 * lane],
                                    Whh[j * 64 + 2 * lane + 1]);
}

// ---------------------------------------------------------------------------
// xg_kernel: xg[tau][j] = sum_d Wc[j][d] * x[tau][d] + bc[j]
// ---------------------------------------------------------------------------
__global__ void __launch_bounds__(256, 2)
xg_kernel(const float* __restrict__ X)
{
    __shared__ __align__(16) float sx[TTOK * 64];
    const int tid = threadIdx.x;
    const int gp  = tid & 127;
    const int th  = tid >> 7;
    const size_t tau0 = (size_t)blockIdx.x * TTOK;

    const float* xf = X + tau0 * DIN;
    for (int i = tid; i < TTOK * DIN; i += 256) {
        float v = xf[i];
        int t = i / DIN, d = i - t * DIN;
        sx[t * 64 + 2 * d]     = v;
        sx[t * 64 + 2 * d + 1] = v;
    }

    ull wA[DIN];
#pragma unroll
    for (int d = 0; d < DIN; ++d)
        wA[d] = pkf2(g_wc[(2 * gp) * DIN + d], g_wc[(2 * gp + 1) * DIN + d]);
    const ull bias2 = pkf2(g_bc[2 * gp], g_bc[2 * gp + 1]);
    __syncthreads();

    float* outp = g_xg + (tau0 + (size_t)th * 32) * 256 + 2 * gp;
#pragma unroll 4
    for (int tt = 0; tt < 32; ++tt) {
        const ulonglong2* xv = (const ulonglong2*)(sx + (th * 32 + tt) * 64);
        ull acc = bias2;
#pragma unroll
        for (int qd = 0; qd < 15; ++qd) {
            ulonglong2 v = xv[qd];
            acc = ffma2(v.x, wA[2 * qd],     acc);
            acc = ffma2(v.y, wA[2 * qd + 1], acc);
        }
        *(ull*)(outp + (size_t)tt * 256) = acc;
    }
}

// ---------------------------------------------------------------------------
// lstm_kernel shared layout (floats)
// ---------------------------------------------------------------------------
#define OFF_H    0      // 512  : h[r*64 + k]
#define OFF_G    512    // 2048 : gates[r*256 + j]
#define OFF_PX   2560   // 2048 : partial exchange [ss][j][4]
#define OFF_WL   4608   // 64
#define OFF_PART 4672   // 16   : logit partials [wid]
#define OFF_LOG  4688   // 4096 : logits [r][512]
#define SMEM_FLOATS 8784

__global__ void __launch_bounds__(NTH, 1)
lstm_kernel(const float* __restrict__ Wlast,
            const float* __restrict__ blast,
            float* __restrict__ out)
{
    __shared__ __align__(16) float s[SMEM_FLOATS];
    const int tid  = threadIdx.x;
    const int lane = tid & 31;
    const int wid  = tid >> 5;
    const int b0   = blockIdx.x * RPB;

    const int j  = tid & 255;   // gate
    const int ss = tid >> 8;    // k-half (warp-uniform: warps 0-7 vs 8-15)

    if (tid < 64) s[OFF_WL + tid] = Wlast[tid];
    s[OFF_H + tid] = 0.0f;   // 512 floats, one per thread

    // weights for this half: kp in [16ss, 16ss+16)
    ull wh[16];
#pragma unroll
    for (int m = 0; m < 16; ++m)
        wh[m] = g_whh_pk[(16 * ss + m) * 256 + j];
    const float blv = blast[0];

    // xg for the 4 rows this thread finalizes (rows 4ss..4ss+3)
    const float* xgp = g_xg + (size_t)(b0 + 4 * ss) * RSTRIDE + j;
    float cur[4];
#pragma unroll
    for (int i = 0; i < 4; ++i) cur[i] = xgp[(size_t)i * RSTRIDE];

    // update role: thread = (row ur, hidden uk), 512 threads = 8x64
    const int ur = tid >> 6, uk = tid & 63;
    const int q  = j >> 6;   // gate quarter (warp-uniform)
    __syncthreads();
    const float wlk = s[OFF_WL + uk];
    float cc = 0.0f;

    for (int t = 0; t < Nseq; ++t) {
        // prefetch xg(t+1)
        float nf[4];
        if (t + 1 < Nseq) {
            const float* p = xgp + (size_t)(t + 1) * 256;
#pragma unroll
            for (int i = 0; i < 4; ++i) nf[i] = p[(size_t)i * RSTRIDE];
        } else {
#pragma unroll
            for (int i = 0; i < 4; ++i) nf[i] = 0.0f;
        }

        // ---- half-k matvec for all 8 rows (broadcast LDS.128 operands) ----
        ull acc[8];
#pragma unroll
        for (int r = 0; r < 8; ++r) acc[r] = 0;
#pragma unroll
        for (int m2 = 0; m2 < 8; ++m2) {
            ull wA = wh[2 * m2], wB = wh[2 * m2 + 1];
#pragma unroll
            for (int r = 0; r < 8; ++r) {
                ulonglong2 hv2 = *(const ulonglong2*)(s + OFF_H + r * 64 + 32 * ss + 4 * m2);
                acc[r] = ffma2(hv2.x, wA, acc[r]);
                acc[r] = ffma2(hv2.y, wB, acc[r]);
            }
        }
        float p0 = sum2(acc[0]), p1 = sum2(acc[1]);
        float p2 = sum2(acc[2]), p3 = sum2(acc[3]);
        float p4 = sum2(acc[4]), p5 = sum2(acc[5]);
        float p6 = sum2(acc[6]), p7 = sum2(acc[7]);

        // donate the other half's rows; keep mine (warp-uniform select)
        float m0, m1, m2v, m3, d0, d1, d2, d3;
        if (ss == 0) { m0 = p0; m1 = p1; m2v = p2; m3 = p3;
                       d0 = p4; d1 = p5; d2 = p6; d3 = p7; }
        else         { m0 = p4; m1 = p5; m2v = p6; m3 = p7;
                       d0 = p0; d1 = p1; d2 = p2; d3 = p3; }
        *(float4*)&s[OFF_PX + ss * 1024 + j * 4] = make_float4(d0, d1, d2, d3);

        __syncthreads();   // bar1: partials exchanged

        float4 gp = *(const float4*)&s[OFF_PX + (1 - ss) * 1024 + j * 4];
        float v0 = m0 + gp.x + cur[0];
        float v1 = m1 + gp.y + cur[1];
        float v2 = m2v + gp.z + cur[2];
        float v3 = m3 + gp.w + cur[3];

        float g0, g1, g2, g3;
        if (q == 2) { g0 = tanh_(v0); g1 = tanh_(v1); g2 = tanh_(v2); g3 = tanh_(v3); }
        else        { g0 = sigm(v0);  g1 = sigm(v1);  g2 = sigm(v2);  g3 = sigm(v3); }
        const int rb = 4 * ss;
        s[OFF_G + (rb + 0) * 256 + j] = g0;
        s[OFF_G + (rb + 1) * 256 + j] = g1;
        s[OFF_G + (rb + 2) * 256 + j] = g2;
        s[OFF_G + (rb + 3) * 256 + j] = g3;

        __syncthreads();   // bar2: gates ready

        // combine previous step's logit partials (8 threads, off hot path)
        if (t > 0 && tid < RPB) {
            s[OFF_LOG + tid * Nseq + (t - 1)] =
                s[OFF_PART + 2 * tid] + s[OFF_PART + 2 * tid + 1] + blv;
        }

        // ---- cell update: all 512 threads, one (row, k) each ----
        float gi  = s[OFF_G + ur * 256 + uk];
        float gf  = s[OFF_G + ur * 256 + uk + 64];
        float ggx = s[OFF_G + ur * 256 + uk + 128];
        float go  = s[OFF_G + ur * 256 + uk + 192];
        cc = fmaf(gf, cc, gi * ggx);
        float hvv = go * tanh_(cc);
        s[OFF_H + ur * 64 + uk] = hvv;

        __syncthreads();   // bar3: h ready

        // logit partial — after bar3, overlaps next step's prefetch/matvec
        float lp = hvv * wlk;
        lp += __shfl_down_sync(0xffffffffu, lp, 16);
        lp += __shfl_down_sync(0xffffffffu, lp, 8);
        lp += __shfl_down_sync(0xffffffffu, lp, 4);
        lp += __shfl_down_sync(0xffffffffu, lp, 2);
        lp += __shfl_down_sync(0xffffffffu, lp, 1);
        if (lane == 0) s[OFF_PART + wid] = lp;   // wid = row*2 + khalf

#pragma unroll
        for (int i = 0; i < 4; ++i) cur[i] = nf[i];
    }

    __syncthreads();
    if (tid < RPB)
        s[OFF_LOG + tid * Nseq + (Nseq - 1)] =
            s[OFF_PART + 2 * tid] + s[OFF_PART + 2 * tid + 1] + blv;
    __syncthreads();

    // ---- softmax over t: warp r handles row r (warps 0-7) ----
    if (wid < RPB) {
        float v[16];
#pragma unroll
        for (int i = 0; i < 16; ++i)
            v[i] = s[OFF_LOG + wid * Nseq + i * 32 + lane];
        float m = v[0];
#pragma unroll
        for (int i = 1; i < 16; ++i) m = fmaxf(m, v[i]);
#pragma unroll
        for (int off = 16; off >= 1; off >>= 1)
            m = fmaxf(m, __shfl_xor_sync(0xffffffffu, m, off));

        float e[16], sum = 0.0f;
#pragma unroll
        for (int i = 0; i < 16; ++i) {
            e[i] = ex2a((v[i] - m) * 1.4426950408889634f);
            sum += e[i];
        }
#pragma unroll
        for (int off = 16; off >= 1; off >>= 1)
            sum += __shfl_xor_sync(0xffffffffu, sum, off);
        const float inv = 1.0f / sum;

        float* orow = out + (size_t)(b0 + wid) * Nseq;
#pragma unroll
        for (int i = 0; i < 16; ++i)
            orow[i * 32 + lane] = e[i] * inv;
    }
}

// ---------------------------------------------------------------------------
extern "C" void kernel_launch(void* const* d_in, const int* in_sizes, int n_in,
                              void* d_out, int out_size) {
    const float* x     = (const float*)d_in[0];
    const float* Wfc   = (const float*)d_in[1];
    const float* bfc   = (const float*)d_in[2];
    const float* Wih   = (const float*)d_in[3];
    const float* Whh   = (const float*)d_in[4];
    const float* bih   = (const float*)d_in[5];
    const float* bhh   = (const float*)d_in[6];
    const float* Wlast = (const float*)d_in[7];
    const float* blast = (const float*)d_in[8];
    float* out = (float*)d_out;

    prep_kernel<<<256, 32>>>(Wfc, bfc, Wih, Whh, bih, bhh);
    xg_kernel<<<(Bsz * Nseq) / TTOK, 256>>>(x);
    lstm_kernel<<<NBLK, NTH>>>(Wlast, blast, out);
}

// round 10
// speedup vs baseline: 1.6430x; 1.0389x over previous
#include <cuda_runtime.h>
#include <cstdint>

// ---------------------------------------------------------------------------
// EnsembleHead fused. B=1024, N=512, D_IN=30, H=64, 4H=256.
// R9: lstm thread = (unit u, k-half ss, row-quad rq). Owns i,f,g,o weights of
// unit u for its k-half (64 u64 regs), computes 4-gate partials for 4 rows,
// swaps half-k partials with tid^64 partner, then LOCAL activation + cell
// update (no gate SMEM traffic, 2 barriers/step). 128 CTAs x 256 thr, 1/SM.
// xg (input GEMM) hoisted; prep parallel.
// ---------------------------------------------------------------------------

typedef unsigned long long ull;

#define Bsz   1024
#define Nseq  512
#define DIN   30
#define RPB   8
#define NBLK  (Bsz / RPB)   // 128
#define MH    32            // k-pairs total
#define TTOK  64
#define RSTRIDE (Nseq * 256)

__device__ float g_wc[256 * DIN];
__device__ float g_bc[256];
__device__ ull   g_whh_pk[MH * 256];   // [m][j] = (Whh[j][2m], Whh[j][2m+1])
__device__ float g_xg[(size_t)Bsz * Nseq * 256];   // 512 MB scratch

// ---------------- helpers ----------------
__device__ __forceinline__ ull pkf2(float a, float b) {
    return (ull)__float_as_uint(a) | ((ull)__float_as_uint(b) << 32);
}
__device__ __forceinline__ ull ffma2(ull a, ull b, ull c) {
    ull d;
    asm("fma.rn.f32x2 %0, %1, %2, %3;" : "=l"(d) : "l"(a), "l"(b), "l"(c));
    return d;
}
__device__ __forceinline__ float sum2(ull v) {
    float lo, hi;
    asm("mov.b64 {%0, %1}, %2;" : "=f"(lo), "=f"(hi) : "l"(v));
    return lo + hi;
}
__device__ __forceinline__ float ex2a(float x) {
    float r; asm("ex2.approx.f32 %0, %1;" : "=f"(r) : "f"(x)); return r;
}
__device__ __forceinline__ float rcpa(float x) {
    float r; asm("rcp.approx.f32 %0, %1;" : "=f"(r) : "f"(x)); return r;
}
__device__ __forceinline__ float sigm(float x) {
    return rcpa(1.0f + ex2a(-1.4426950408889634f * x));
}
__device__ __forceinline__ float tanh_(float x) {
    return fmaf(2.0f, rcpa(1.0f + ex2a(-2.8853900817779268f * x)), -1.0f);
}

// ---------------------------------------------------------------------------
// prep (parallel): grid=256 (j), block=32.
// ---------------------------------------------------------------------------
__global__ void prep_kernel(const float* __restrict__ Wfc,
                            const float* __restrict__ bfc,
                            const float* __restrict__ Wih,
                            const float* __restrict__ Whh,
                            const float* __restrict__ bih,
                            const float* __restrict__ bhh)
{
    const int j = blockIdx.x;
    const int lane = threadIdx.x;

    const float w1 = Wih[j * 64 + lane];
    const float w2 = Wih[j * 64 + lane + 32];
    float acc[DIN];
#pragma unroll
    for (int d = 0; d < DIN; ++d)
        acc[d] = w1 * Wfc[lane * DIN + d] + w2 * Wfc[(lane + 32) * DIN + d];
    float bs = w1 * bfc[lane] + w2 * bfc[lane + 32];

#pragma unroll
    for (int off = 16; off >= 1; off >>= 1) {
#pragma unroll
        for (int d = 0; d < DIN; ++d)
            acc[d] += __shfl_xor_sync(0xffffffffu, acc[d], off);
        bs += __shfl_xor_sync(0xffffffffu, bs, off);
    }

    if (lane == 0) {
#pragma unroll
        for (int d = 0; d < DIN; ++d) g_wc[j * DIN + d] = acc[d];
        g_bc[j] = bs + bih[j] + bhh[j];
    }
    g_whh_pk[lane * 256 + j] = pkf2(Whh[j * 64 + 2 * lane],
                                    Whh[j * 64 + 2 * lane + 1]);
}

// ---------------------------------------------------------------------------
// xg_kernel: xg[tau][j] = sum_d Wc[j][d] * x[tau][d] + bc[j]
// ---------------------------------------------------------------------------
__global__ void __launch_bounds__(256, 2)
xg_kernel(const float* __restrict__ X)
{
    __shared__ __align__(16) float sx[TTOK * 64];
    const int tid = threadIdx.x;
    const int gp  = tid & 127;
    const int th  = tid >> 7;
    const size_t tau0 = (size_t)blockIdx.x * TTOK;

    const float* xf = X + tau0 * DIN;
    for (int i = tid; i < TTOK * DIN; i += 256) {
        float v = xf[i];
        int t = i / DIN, d = i - t * DIN;
        sx[t * 64 + 2 * d]     = v;
        sx[t * 64 + 2 * d + 1] = v;
    }

    ull wA[DIN];
#pragma unroll
    for (int d = 0; d < DIN; ++d)
        wA[d] = pkf2(g_wc[(2 * gp) * DIN + d], g_wc[(2 * gp + 1) * DIN + d]);
    const ull bias2 = pkf2(g_bc[2 * gp], g_bc[2 * gp + 1]);
    __syncthreads();

    float* outp = g_xg + (tau0 + (size_t)th * 32) * 256 + 2 * gp;
#pragma unroll 4
    for (int tt = 0; tt < 32; ++tt) {
        const ulonglong2* xv = (const ulonglong2*)(sx + (th * 32 + tt) * 64);
        ull acc = bias2;
#pragma unroll
        for (int qd = 0; qd < 15; ++qd) {
            ulonglong2 v = xv[qd];
            acc = ffma2(v.x, wA[2 * qd],     acc);
            acc = ffma2(v.y, wA[2 * qd + 1], acc);
        }
        *(ull*)(outp + (size_t)tt * 256) = acc;
    }
}

// ---------------------------------------------------------------------------
// lstm_kernel shared layout (floats)
// ---------------------------------------------------------------------------
#define OFF_H    0      // 512  : h[row*64 + u]
#define OFF_PX   512    // 3072 : partial exchange, slot = tid*12 (8 used)
#define OFF_WL   3584   // 64
#define OFF_PART 3648   // 16   : logit partials [row*2 + uh]
#define OFF_LOG  3664   // 4096 : logits [row][512]
#define SMEM_FLOATS 7760

__global__ void __launch_bounds__(256, 1)
lstm_kernel(const float* __restrict__ Wlast,
            const float* __restrict__ blast,
            float* __restrict__ out)
{
    __shared__ __align__(16) float s[SMEM_FLOATS];
    const int tid  = threadIdx.x;
    const int lane = tid & 31;
    const int wid  = tid >> 5;
    const int b0   = blockIdx.x * RPB;

    const int u  = tid & 63;          // hidden unit
    const int ss = (tid >> 6) & 1;    // k-half (warp-uniform)
    const int rq = tid >> 7;          // row quad (warp-uniform)
    const int uh = (tid >> 5) & 1;    // u-half within unit group

    if (tid < 64) s[OFF_WL + tid] = Wlast[tid];
    s[OFF_H + tid] = 0.0f;
    s[OFF_H + 256 + tid] = 0.0f;

    // weights: gates {u, u+64, u+128, u+192}, k-pairs [16ss, 16ss+16)
    ull wh[64];   // wh[gi*16 + m]
#pragma unroll
    for (int gi = 0; gi < 4; ++gi)
#pragma unroll
        for (int m = 0; m < 16; ++m)
            wh[gi * 16 + m] = g_whh_pk[(16 * ss + m) * 256 + gi * 64 + u];

    const float blv = blast[0];

    // rows: A,B = finalized by this thread; C,D = donated to partner (tid^64)
    const int rowA = 4 * rq + 2 * ss;
    const int rowB = rowA + 1;
    const int rowC = 4 * rq + 2 * (1 - ss);
    const int rowD = rowC + 1;
    const int kb   = 32 * ss;   // float offset of this k-half in an h row

    // xg pointers for own rows (gate gi at offset gi*64)
    const float* xgA = g_xg + (size_t)(b0 + rowA) * RSTRIDE + u;
    const float* xgB = g_xg + (size_t)(b0 + rowB) * RSTRIDE + u;
    float curA[4], curB[4];
#pragma unroll
    for (int gi = 0; gi < 4; ++gi) {
        curA[gi] = xgA[gi * 64];
        curB[gi] = xgB[gi * 64];
    }

    __syncthreads();
    const float wlu = s[OFF_WL + u];
    float ccA = 0.0f, ccB = 0.0f;

    for (int t = 0; t < Nseq; ++t) {
        // prefetch xg(t+1) for own rows
        float nfA[4], nfB[4];
        if (t + 1 < Nseq) {
            const float* pA = xgA + (size_t)(t + 1) * 256;
            const float* pB = xgB + (size_t)(t + 1) * 256;
#pragma unroll
            for (int gi = 0; gi < 4; ++gi) {
                nfA[gi] = pA[gi * 64];
                nfB[gi] = pB[gi * 64];
            }
        } else {
#pragma unroll
            for (int gi = 0; gi < 4; ++gi) { nfA[gi] = 0.f; nfB[gi] = 0.f; }
        }

        // ---- half-k matvec: 4 gates x 4 rows (A,B,C,D) ----
        ull aA[4], aB[4], aC[4], aD[4];
#pragma unroll
        for (int gi = 0; gi < 4; ++gi) { aA[gi] = 0; aB[gi] = 0; aC[gi] = 0; aD[gi] = 0; }

#pragma unroll
        for (int m4 = 0; m4 < 8; ++m4) {
            ulonglong2 hA = *(const ulonglong2*)(s + OFF_H + rowA * 64 + kb + 4 * m4);
            ulonglong2 hB = *(const ulonglong2*)(s + OFF_H + rowB * 64 + kb + 4 * m4);
            ulonglong2 hC = *(const ulonglong2*)(s + OFF_H + rowC * 64 + kb + 4 * m4);
            ulonglong2 hD = *(const ulonglong2*)(s + OFF_H + rowD * 64 + kb + 4 * m4);
#pragma unroll
            for (int gi = 0; gi < 4; ++gi) {
                const ull w0 = wh[gi * 16 + 2 * m4];
                const ull w1 = wh[gi * 16 + 2 * m4 + 1];
                aA[gi] = ffma2(hA.x, w0, aA[gi]); aA[gi] = ffma2(hA.y, w1, aA[gi]);
                aB[gi] = ffma2(hB.x, w0, aB[gi]); aB[gi] = ffma2(hB.y, w1, aB[gi]);
                aC[gi] = ffma2(hC.x, w0, aC[gi]); aC[gi] = ffma2(hC.y, w1, aC[gi]);
                aD[gi] = ffma2(hD.x, w0, aD[gi]); aD[gi] = ffma2(hD.y, w1, aD[gi]);
            }
        }

        // donate rows C,D partials to partner (its own rows)
        {
            float4 dc = make_float4(sum2(aC[0]), sum2(aC[1]), sum2(aC[2]), sum2(aC[3]));
            float4 dd = make_float4(sum2(aD[0]), sum2(aD[1]), sum2(aD[2]), sum2(aD[3]));
            float* slot = &s[OFF_PX + (tid ^ 64) * 12];
            *(float4*)(slot)     = dc;
            *(float4*)(slot + 4) = dd;
        }

        __syncthreads();   // bar1: partials exchanged (+ prev PART stable)

        // combine previous step's logit partials (8 threads, off hot path)
        if (t > 0 && tid < RPB)
            s[OFF_LOG + tid * Nseq + (t - 1)] =
                s[OFF_PART + 2 * tid] + s[OFF_PART + 2 * tid + 1] + blv;

        // full preacts for own rows A,B
        float4 qa = *(const float4*)&s[OFF_PX + tid * 12];
        float4 qb = *(const float4*)&s[OFF_PX + tid * 12 + 4];

        float viA = sum2(aA[0]) + qa.x + curA[0];
        float vfA = sum2(aA[1]) + qa.y + curA[1];
        float vgA = sum2(aA[2]) + qa.z + curA[2];
        float voA = sum2(aA[3]) + qa.w + curA[3];
        float viB = sum2(aB[0]) + qb.x + curB[0];
        float vfB = sum2(aB[1]) + qb.y + curB[1];
        float vgB = sum2(aB[2]) + qb.z + curB[2];
        float voB = sum2(aB[3]) + qb.w + curB[3];

        // local activation + cell update (no branch, no gate SMEM)
        float iA = sigm(viA), fA = sigm(vfA), gA = tanh_(vgA), oA = sigm(voA);
        float iB = sigm(viB), fB = sigm(vfB), gB = tanh_(vgB), oB = sigm(voB);
        ccA = fmaf(fA, ccA, iA * gA);
        ccB = fmaf(fB, ccB, iB * gB);
        float hvA = oA * tanh_(ccA);
        float hvB = oB * tanh_(ccB);
        s[OFF_H + rowA * 64 + u] = hvA;
        s[OFF_H + rowB * 64 + u] = hvB;

        __syncthreads();   // bar2: h ready

        // logit partials -- after bar2, overlaps next step's prefetch/matvec
        float p0 = hvA * wlu;
        float p1 = hvB * wlu;
#pragma unroll
        for (int off = 16; off >= 1; off >>= 1) {
            p0 += __shfl_down_sync(0xffffffffu, p0, off);
            p1 += __shfl_down_sync(0xffffffffu, p1, off);
        }
        if (lane == 0) {
            s[OFF_PART + rowA * 2 + uh] = p0;
            s[OFF_PART + rowB * 2 + uh] = p1;
        }

#pragma unroll
        for (int gi = 0; gi < 4; ++gi) { curA[gi] = nfA[gi]; curB[gi] = nfB[gi]; }
    }

    __syncthreads();
    if (tid < RPB)
        s[OFF_LOG + tid * Nseq + (Nseq - 1)] =
            s[OFF_PART + 2 * tid] + s[OFF_PART + 2 * tid + 1] + blv;
    __syncthreads();

    // ---- softmax over t: warp r handles row r (8 warps) ----
    {
        float v[16];
#pragma unroll
        for (int i = 0; i < 16; ++i)
            v[i] = s[OFF_LOG + wid * Nseq + i * 32 + lane];
        float m = v[0];
#pragma unroll
        for (int i = 1; i < 16; ++i) m = fmaxf(m, v[i]);
#pragma unroll
        for (int off = 16; off >= 1; off >>= 1)
            m = fmaxf(m, __shfl_xor_sync(0xffffffffu, m, off));

        float e[16], sum = 0.0f;
#pragma unroll
        for (int i = 0; i < 16; ++i) {
            e[i] = ex2a((v[i] - m) * 1.4426950408889634f);
            sum += e[i];
        }
#pragma unroll
        for (int off = 16; off >= 1; off >>= 1)
            sum += __shfl_xor_sync(0xffffffffu, sum, off);
        const float inv = 1.0f / sum;

        float* orow = out + (size_t)(b0 + wid) * Nseq;
#pragma unroll
        for (int i = 0; i < 16; ++i)
            orow[i * 32 + lane] = e[i] * inv;
    }
}

// ---------------------------------------------------------------------------
extern "C" void kernel_launch(void* const* d_in, const int* in_sizes, int n_in,
                              void* d_out, int out_size) {
    const float* x     = (const float*)d_in[0];
    const float* Wfc   = (const float*)d_in[1];
    const float* bfc   = (const float*)d_in[2];
    const float* Wih   = (const float*)d_in[3];
    const float* Whh   = (const float*)d_in[4];
    const float* bih   = (const float*)d_in[5];
    const float* bhh   = (const float*)d_in[6];
    const float* Wlast = (const float*)d_in[7];
    const float* blast = (const float*)d_in[8];
    float* out = (float*)d_out;

    prep_kernel<<<256, 32>>>(Wfc, bfc, Wih, Whh, bih, bhh);
    xg_kernel<<<(Bsz * Nseq) / TTOK, 256>>>(x);
    lstm_kernel<<<NBLK, 256>>>(Wlast, blast, out);
}

// round 11
// speedup vs baseline: 2.5656x; 1.5616x over previous
#include <cuda_runtime.h>
#include <cuda_fp16.h>
#include <cstdint>

// ---------------------------------------------------------------------------
// EnsembleHead fused. B=1024, N=512, D_IN=30, H=64, 4H=256.
// R10: recurrence matvec on the TENSOR pipe (mma.sync m16n8k16 fp16->fp32).
// fp32 scalar pipe was the ~1ms roofline (FFMA2 has no throughput gain).
// xg (input GEMM, exact fp32) hoisted, layout [cta][t][row][gate].
// lstm: 128 CTAs x 256 thr; W_hh fp16 B-frags in regs; h fp16 in SMEM.
// ---------------------------------------------------------------------------

typedef unsigned long long ull;
typedef unsigned int uint32;

#define Bsz   1024
#define Nseq  512
#define DIN   30
#define RPB   8
#define NBLK  (Bsz / RPB)   // 128
#define TTOK  64

#define LDH   72            // h_fp16 row stride in halfs (bank-skewed)
#define LDP   264           // s_pre row stride in floats (bank-skewed)

__device__ float  g_wc[256 * DIN];
__device__ float  g_bc[256];
__device__ __half g_whh_h[256 * 64];                // W_hh fp16, [n][k]
__device__ float  g_xg[(size_t)Bsz * Nseq * 256];   // [cta][t][r][gate]

// ---------------- helpers ----------------
__device__ __forceinline__ ull pkf2(float a, float b) {
    return (ull)__float_as_uint(a) | ((ull)__float_as_uint(b) << 32);
}
__device__ __forceinline__ ull ffma2(ull a, ull b, ull c) {
    ull d;
    asm("fma.rn.f32x2 %0, %1, %2, %3;" : "=l"(d) : "l"(a), "l"(b), "l"(c));
    return d;
}
__device__ __forceinline__ float ex2a(float x) {
    float r; asm("ex2.approx.f32 %0, %1;" : "=f"(r) : "f"(x)); return r;
}
__device__ __forceinline__ float rcpa(float x) {
    float r; asm("rcp.approx.f32 %0, %1;" : "=f"(r) : "f"(x)); return r;
}
__device__ __forceinline__ float sigm(float x) {
    return rcpa(1.0f + ex2a(-1.4426950408889634f * x));
}
__device__ __forceinline__ float tanh_(float x) {
    return fmaf(2.0f, rcpa(1.0f + ex2a(-2.8853900817779268f * x)), -1.0f);
}
__device__ __forceinline__ void mma16816(float* c, const uint32* a,
                                         uint32 b0, uint32 b1) {
    asm volatile(
        "mma.sync.aligned.m16n8k16.row.col.f32.f16.f16.f32 "
        "{%0,%1,%2,%3}, {%4,%5,%6,%7}, {%8,%9}, {%0,%1,%2,%3};"
        : "+f"(c[0]), "+f"(c[1]), "+f"(c[2]), "+f"(c[3])
        : "r"(a[0]), "r"(a[1]), "r"(a[2]), "r"(a[3]), "r"(b0), "r"(b1));
}

// ---------------------------------------------------------------------------
// prep (parallel): grid=256 (j), block=32.
// ---------------------------------------------------------------------------
__global__ void prep_kernel(const float* __restrict__ Wfc,
                            const float* __restrict__ bfc,
                            const float* __restrict__ Wih,
                            const float* __restrict__ Whh,
                            const float* __restrict__ bih,
                            const float* __restrict__ bhh)
{
    const int j = blockIdx.x;
    const int lane = threadIdx.x;

    const float w1 = Wih[j * 64 + lane];
    const float w2 = Wih[j * 64 + lane + 32];
    float acc[DIN];
#pragma unroll
    for (int d = 0; d < DIN; ++d)
        acc[d] = w1 * Wfc[lane * DIN + d] + w2 * Wfc[(lane + 32) * DIN + d];
    float bs = w1 * bfc[lane] + w2 * bfc[lane + 32];

#pragma unroll
    for (int off = 16; off >= 1; off >>= 1) {
#pragma unroll
        for (int d = 0; d < DIN; ++d)
            acc[d] += __shfl_xor_sync(0xffffffffu, acc[d], off);
        bs += __shfl_xor_sync(0xffffffffu, bs, off);
    }

    if (lane == 0) {
#pragma unroll
        for (int d = 0; d < DIN; ++d) g_wc[j * DIN + d] = acc[d];
        g_bc[j] = bs + bih[j] + bhh[j];
    }
    // W_hh to fp16: lane covers k = 2*lane, 2*lane+1
    g_whh_h[j * 64 + 2 * lane]     = __float2half(Whh[j * 64 + 2 * lane]);
    g_whh_h[j * 64 + 2 * lane + 1] = __float2half(Whh[j * 64 + 2 * lane + 1]);
}

// ---------------------------------------------------------------------------
// xg_kernel: xg = x @ Wc^T + bc (fp32), layout [cta][t][r][gate]
// ---------------------------------------------------------------------------
__global__ void __launch_bounds__(256, 2)
xg_kernel(const float* __restrict__ X)
{
    __shared__ __align__(16) float sx[TTOK * 64];
    const int tid = threadIdx.x;
    const int gp  = tid & 127;
    const int th  = tid >> 7;
    const size_t tau0 = (size_t)blockIdx.x * TTOK;   // all tokens share b
    const int b  = (int)(tau0 >> 9);
    const int t0 = (int)(tau0 & 511);

    const float* xf = X + tau0 * DIN;
    for (int i = tid; i < TTOK * DIN; i += 256) {
        float v = xf[i];
        int t = i / DIN, d = i - t * DIN;
        sx[t * 64 + 2 * d]     = v;
        sx[t * 64 + 2 * d + 1] = v;
    }

    ull wA[DIN];
#pragma unroll
    for (int d = 0; d < DIN; ++d)
        wA[d] = pkf2(g_wc[(2 * gp) * DIN + d], g_wc[(2 * gp + 1) * DIN + d]);
    const ull bias2 = pkf2(g_bc[2 * gp], g_bc[2 * gp + 1]);
    __syncthreads();

    // out: ((b>>3)*512 + t)*2048 + (b&7)*256 + j
    float* outp = g_xg + ((size_t)(b >> 3) * 512 + t0) * 2048
                       + (size_t)(b & 7) * 256 + 2 * gp;
#pragma unroll 4
    for (int tt = 0; tt < 32; ++tt) {
        const ulonglong2* xv = (const ulonglong2*)(sx + (th * 32 + tt) * 64);
        ull acc = bias2;
#pragma unroll
        for (int qd = 0; qd < 15; ++qd) {
            ulonglong2 v = xv[qd];
            acc = ffma2(v.x, wA[2 * qd],     acc);
            acc = ffma2(v.y, wA[2 * qd + 1], acc);
        }
        *(ull*)(outp + (size_t)(th * 32 + tt) * 2048) = acc;
    }
}

// ---------------------------------------------------------------------------
// lstm_kernel: tensor-pipe recurrence. 128 CTAs x 256 thr (8 warps).
// warp w: mma n-slice gates [32w, 32w+32); gid=lane>>2 (row), tig=lane&3.
// cell role: u=tid&63, rows r1=tid>>6 and r1+4.
// ---------------------------------------------------------------------------
__global__ void __launch_bounds__(256, 1)
lstm_kernel(const float* __restrict__ Wlast,
            const float* __restrict__ blast,
            float* __restrict__ out)
{
    __shared__ __align__(16) __half sh[16 * LDH];      // h fp16, rows 8-15 zero
    __shared__ __align__(16) float  s_pre[8 * LDP];    // gate preacts
    __shared__ float s_wl[64];
    __shared__ float s_part[16];                       // [row*2 + uhalf]
    __shared__ float s_log[RPB * Nseq];

    const int tid  = threadIdx.x;
    const int lane = tid & 31;
    const int wid  = tid >> 5;
    const int b0   = blockIdx.x * RPB;

    // init
    {
        uint32* shz = (uint32*)sh;
        for (int i = tid; i < 16 * LDH / 2; i += 256) shz[i] = 0;
        if (tid < 64) s_wl[tid] = Wlast[tid];
    }
    const float blv = blast[0];

    // ---- mma role ----
    const int gid = lane >> 2;     // row (0-7)
    const int tig = lane & 3;
    const int nbase = wid * 32;

    // B fragments: W_hh fp16 [n][k]; b[nt][kt][2]
    uint32 bfr[4][4][2];
#pragma unroll
    for (int nt = 0; nt < 4; ++nt)
#pragma unroll
        for (int kt = 0; kt < 4; ++kt) {
            const int n0 = nbase + nt * 8 + gid;
            const int k0 = kt * 16 + tig * 2;
            bfr[nt][kt][0] = *(const uint32*)(g_whh_h + n0 * 64 + k0);
            bfr[nt][kt][1] = *(const uint32*)(g_whh_h + n0 * 64 + k0 + 8);
        }

    // xg pointers: [cta][t][r=gid][gate]
    const float* xgp = g_xg + (size_t)blockIdx.x * Nseq * 2048
                            + (size_t)gid * 256 + nbase + tig * 2;
    float2 cur[4], nf[4];
#pragma unroll
    for (int nt = 0; nt < 4; ++nt)
        cur[nt] = *(const float2*)(xgp + nt * 8);

    // ---- cell role ----
    const int u  = tid & 63;
    const int r1 = tid >> 6;       // 0-3; also handles r1+4
    const int uh = wid & 1;
    __syncthreads();
    const float wlu = s_wl[u];
    float cc1 = 0.0f, cc2 = 0.0f;

    for (int t = 0; t < Nseq; ++t) {
        // prefetch xg(t+1)
        if (t + 1 < Nseq) {
            const float* p = xgp + (size_t)(t + 1) * 2048;
#pragma unroll
            for (int nt = 0; nt < 4; ++nt) nf[nt] = *(const float2*)(p + nt * 8);
        } else {
#pragma unroll
            for (int nt = 0; nt < 4; ++nt) nf[nt] = make_float2(0.f, 0.f);
        }

        // ---- A fragments from h fp16 (conflict-free LDS.32) ----
        uint32 afr[4][4];
#pragma unroll
        for (int kt = 0; kt < 4; ++kt) {
            const int cb = kt * 16 + tig * 2;
            afr[kt][0] = *(const uint32*)(sh + gid * LDH + cb);
            afr[kt][1] = *(const uint32*)(sh + (gid + 8) * LDH + cb);
            afr[kt][2] = *(const uint32*)(sh + gid * LDH + cb + 8);
            afr[kt][3] = *(const uint32*)(sh + (gid + 8) * LDH + cb + 8);
        }

        // ---- tensor matvec: h @ Whh^T for this warp's 32 gates ----
        float cfr[4][4];
#pragma unroll
        for (int nt = 0; nt < 4; ++nt) {
            cfr[nt][0] = 0.f; cfr[nt][1] = 0.f; cfr[nt][2] = 0.f; cfr[nt][3] = 0.f;
#pragma unroll
            for (int kt = 0; kt < 4; ++kt)
                mma16816(cfr[nt], afr[kt], bfr[nt][kt][0], bfr[nt][kt][1]);
        }

        // preact = mma + xg; store to s_pre[row gid]
#pragma unroll
        for (int nt = 0; nt < 4; ++nt) {
            float2 pr;
            pr.x = cfr[nt][0] + cur[nt].x;
            pr.y = cfr[nt][1] + cur[nt].y;
            *(float2*)&s_pre[gid * LDP + nbase + nt * 8 + tig * 2] = pr;
        }

        __syncthreads();   // bar1: preacts ready (also protects s_part)

        // combine previous step's logit partials (8 threads)
        if (t > 0 && tid < RPB)
            s_log[tid * Nseq + (t - 1)] =
                s_part[2 * tid] + s_part[2 * tid + 1] + blv;

        // ---- cell update: rows r1 and r1+4, unit u ----
        float i1 = s_pre[r1 * LDP + u];
        float f1 = s_pre[r1 * LDP + u + 64];
        float g1 = s_pre[r1 * LDP + u + 128];
        float o1 = s_pre[r1 * LDP + u + 192];
        float i2 = s_pre[(r1 + 4) * LDP + u];
        float f2 = s_pre[(r1 + 4) * LDP + u + 64];
        float g2 = s_pre[(r1 + 4) * LDP + u + 128];
        float o2 = s_pre[(r1 + 4) * LDP + u + 192];

        i1 = sigm(i1); f1 = sigm(f1); g1 = tanh_(g1); o1 = sigm(o1);
        i2 = sigm(i2); f2 = sigm(f2); g2 = tanh_(g2); o2 = sigm(o2);
        cc1 = fmaf(f1, cc1, i1 * g1);
        cc2 = fmaf(f2, cc2, i2 * g2);
        float hv1 = o1 * tanh_(cc1);
        float hv2 = o2 * tanh_(cc2);
        sh[r1 * LDH + u]       = __float2half(hv1);
        sh[(r1 + 4) * LDH + u] = __float2half(hv2);

        __syncthreads();   // bar2: h ready

        // logit partials (warp covers one u-half of rows r1, r1+4)
        float p1 = hv1 * wlu;
        float p2 = hv2 * wlu;
#pragma unroll
        for (int off = 16; off >= 1; off >>= 1) {
            p1 += __shfl_down_sync(0xffffffffu, p1, off);
            p2 += __shfl_down_sync(0xffffffffu, p2, off);
        }
        if (lane == 0) {
            s_part[r1 * 2 + uh]       = p1;
            s_part[(r1 + 4) * 2 + uh] = p2;
        }

#pragma unroll
        for (int nt = 0; nt < 4; ++nt) cur[nt] = nf[nt];
    }

    __syncthreads();
    if (tid < RPB)
        s_log[tid * Nseq + (Nseq - 1)] =
            s_part[2 * tid] + s_part[2 * tid + 1] + blv;
    __syncthreads();

    // ---- softmax over t: warp r handles row r ----
    {
        float v[16];
#pragma unroll
        for (int i = 0; i < 16; ++i)
            v[i] = s_log[wid * Nseq + i * 32 + lane];
        float m = v[0];
#pragma unroll
        for (int i = 1; i < 16; ++i) m = fmaxf(m, v[i]);
#pragma unroll
        for (int off = 16; off >= 1; off >>= 1)
            m = fmaxf(m, __shfl_xor_sync(0xffffffffu, m, off));

        float e[16], sum = 0.0f;
#pragma unroll
        for (int i = 0; i < 16; ++i) {
            e[i] = ex2a((v[i] - m) * 1.4426950408889634f);
            sum += e[i];
        }
#pragma unroll
        for (int off = 16; off >= 1; off >>= 1)
            sum += __shfl_xor_sync(0xffffffffu, sum, off);
        const float inv = 1.0f / sum;

        float* orow = out + (size_t)(b0 + wid) * Nseq;
#pragma unroll
        for (int i = 0; i < 16; ++i)
            orow[i * 32 + lane] = e[i] * inv;
    }
}

// ---------------------------------------------------------------------------
extern "C" void kernel_launch(void* const* d_in, const int* in_sizes, int n_in,
                              void* d_out, int out_size) {
    const float* x     = (const float*)d_in[0];
    const float* Wfc   = (const float*)d_in[1];
    const float* bfc   = (const float*)d_in[2];
    const float* Wih   = (const float*)d_in[3];
    const float* Whh   = (const float*)d_in[4];
    const float* bih   = (const float*)d_in[5];
    const float* bhh   = (const float*)d_in[6];
    const float* Wlast = (const float*)d_in[7];
    const float* blast = (const float*)d_in[8];
    float* out = (float*)d_out;

    prep_kernel<<<256, 32>>>(Wfc, bfc, Wih, Whh, bih, bhh);
    xg_kernel<<<(Bsz * Nseq) / TTOK, 256>>>(x);
    lstm_kernel<<<NBLK, 256>>>(Wlast, blast, out);
}

// round 12
// speedup vs baseline: 6.6141x; 2.5780x over previous
#include <cuda_runtime.h>
#include <cuda_fp16.h>
#include <cstdint>

// ---------------------------------------------------------------------------
// EnsembleHead fused. B=1024, N=512, D_IN=30, H=64, 4H=256.
// R11: SINGLE-PASS recurrence on the tensor pipe with fused input GEMM:
//   preact = [h_t, x_t](fp16, k=96) @ [W_hh ; W_comb]^T(fp16) + b
// Warp w owns n-tiles {gi*64+8w} for gi=0..3, so each thread holds all four
// gates of its 2 units -> LOCAL activation+cell update, ONE barrier/step.
// No xg scratch, no 1GB DRAM round trip. 128 CTAs x 256 thr, 1/SM.
// ---------------------------------------------------------------------------

typedef unsigned long long ull;
typedef unsigned int uint32;

#define Bsz   1024
#define Nseq  512
#define DIN   30
#define RPB   8
#define NBLK  (Bsz / RPB)   // 128
#define KTOT  96            // 64 h + 32 x (30 used)
#define LDH   104           // halfs per SMEM row (bank-skewed)

__device__ __half g_wcomb_h[256 * KTOT];  // [n][k]: k<64 Whh, 64..93 Wc, 94/95 = 0
__device__ float  g_bc[256];

// ---------------- helpers ----------------
__device__ __forceinline__ float ex2a(float x) {
    float r; asm("ex2.approx.f32 %0, %1;" : "=f"(r) : "f"(x)); return r;
}
__device__ __forceinline__ float rcpa(float x) {
    float r; asm("rcp.approx.f32 %0, %1;" : "=f"(r) : "f"(x)); return r;
}
__device__ __forceinline__ float sigm(float x) {
    return rcpa(1.0f + ex2a(-1.4426950408889634f * x));
}
__device__ __forceinline__ float tanh_(float x) {
    return fmaf(2.0f, rcpa(1.0f + ex2a(-2.8853900817779268f * x)), -1.0f);
}
__device__ __forceinline__ void mma16816(float* c, uint32 a0, uint32 a1,
                                         uint32 a2, uint32 a3,
                                         uint32 b0, uint32 b1) {
    asm volatile(
        "mma.sync.aligned.m16n8k16.row.col.f32.f16.f16.f32 "
        "{%0,%1,%2,%3}, {%4,%5,%6,%7}, {%8,%9}, {%0,%1,%2,%3};"
        : "+f"(c[0]), "+f"(c[1]), "+f"(c[2]), "+f"(c[3])
        : "r"(a0), "r"(a1), "r"(a2), "r"(a3), "r"(b0), "r"(b1));
}

// ---------------------------------------------------------------------------
// prep: build combined fp16 weight [n][96] = [Whh | Wih@Wfc | 0] and bias.
// grid=256 (n), block=32.
// ---------------------------------------------------------------------------
__global__ void prep_kernel(const float* __restrict__ Wfc,
                            const float* __restrict__ bfc,
                            const float* __restrict__ Wih,
                            const float* __restrict__ Whh,
                            const float* __restrict__ bih,
                            const float* __restrict__ bhh)
{
    const int j = blockIdx.x;
    const int lane = threadIdx.x;

    const float w1 = Wih[j * 64 + lane];
    const float w2 = Wih[j * 64 + lane + 32];
    float acc[DIN];
#pragma unroll
    for (int d = 0; d < DIN; ++d)
        acc[d] = w1 * Wfc[lane * DIN + d] + w2 * Wfc[(lane + 32) * DIN + d];
    float bs = w1 * bfc[lane] + w2 * bfc[lane + 32];

#pragma unroll
    for (int off = 16; off >= 1; off >>= 1) {
#pragma unroll
        for (int d = 0; d < DIN; ++d)
            acc[d] += __shfl_xor_sync(0xffffffffu, acc[d], off);
        bs += __shfl_xor_sync(0xffffffffu, bs, off);
    }

    // Whh region: lane covers k = 2lane, 2lane+1
    g_wcomb_h[j * KTOT + 2 * lane]     = __float2half(Whh[j * 64 + 2 * lane]);
    g_wcomb_h[j * KTOT + 2 * lane + 1] = __float2half(Whh[j * 64 + 2 * lane + 1]);

    // Wc region: lane l covers cols 64+2l, 64+2l+1 (static selects, no LDL)
    float a0 = 0.0f, a1 = 0.0f;
#pragma unroll
    for (int d = 0; d < DIN; ++d) {
        if (d == 2 * lane)     a0 = acc[d];
        if (d == 2 * lane + 1) a1 = acc[d];
    }
    if (lane < 16) {   // lane 15 writes zeros to cols 94,95
        g_wcomb_h[j * KTOT + 64 + 2 * lane]     = __float2half(a0);
        g_wcomb_h[j * KTOT + 64 + 2 * lane + 1] = __float2half(a1);
    }
    if (lane == 0) g_bc[j] = bs + bih[j] + bhh[j];
}

// ---------------------------------------------------------------------------
// lstm_kernel: 128 CTAs x 256 thr (8 warps), 1/SM.
// thread (wid, gid=lane>>2, tig=lane&3): row gid, units u0=wid*8+tig*2, u0+1.
// ---------------------------------------------------------------------------
__global__ void __launch_bounds__(256, 1)
lstm_kernel(const float* __restrict__ X,
            const float* __restrict__ Wlast,
            const float* __restrict__ blast,
            float* __restrict__ out)
{
    __shared__ __align__(16) __half sh[2][RPB][LDH];  // [buf][row][k]: h 0..63, x 64..95
    __shared__ float s_wl[64];
    __shared__ float s_part[2][RPB][8];               // [parity][row][warp]
    __shared__ float s_log[RPB * Nseq];

    const int tid  = threadIdx.x;
    const int lane = tid & 31;
    const int wid  = tid >> 5;
    const int b0   = blockIdx.x * RPB;
    const int gid  = lane >> 2;
    const int tig  = lane & 3;

    // zero both SMEM buffers (h and x pad regions), load Wlast
    for (int i = tid; i < 2 * RPB * LDH / 2; i += 256) ((uint32*)sh)[i] = 0;
    if (tid < 64) s_wl[tid] = Wlast[tid];
    const float blv = blast[0];

    // B fragments: combined weight, n0 = gi*64 + wid*8 + gid
    uint32 bfr[4][6][2];
#pragma unroll
    for (int gi = 0; gi < 4; ++gi)
#pragma unroll
        for (int kt = 0; kt < 6; ++kt) {
            const int n0 = gi * 64 + wid * 8 + gid;
            const int k0 = kt * 16 + tig * 2;
            bfr[gi][kt][0] = *(const uint32*)(g_wcomb_h + n0 * KTOT + k0);
            bfr[gi][kt][1] = *(const uint32*)(g_wcomb_h + n0 * KTOT + k0 + 8);
        }
    // biases for this thread's 2 units x 4 gates
    float bia[4][2];
#pragma unroll
    for (int gi = 0; gi < 4; ++gi) {
        bia[gi][0] = g_bc[gi * 64 + wid * 8 + tig * 2];
        bia[gi][1] = g_bc[gi * 64 + wid * 8 + tig * 2 + 1];
    }

    // x prefetch role: tid<240 owns (row, d)
    const bool px = tid < RPB * DIN;
    const int prow = tid / DIN;
    const int pd   = tid - prow * DIN;
    const float* xp = X + ((size_t)(b0 + prow) * Nseq) * DIN + pd;

    __syncthreads();   // zero-fill complete before x(0) staging
    if (px) sh[0][prow][64 + pd] = __float2half(xp[0]);
    __syncthreads();

    const float wl0 = s_wl[wid * 8 + tig * 2];
    const float wl1 = s_wl[wid * 8 + tig * 2 + 1];
    float cc0 = 0.0f, cc1 = 0.0f;

    for (int t = 0; t < Nseq; ++t) {
        const int buf = t & 1;

        // prefetch x(t+1)
        float xv = 0.0f;
        const bool pf = px && (t + 1 < Nseq);
        if (pf) xv = xp[(t + 1) * DIN];

        // A fragments (rows 8-15 are zero -> a1=a3=0)
        uint32 afr0[6], afr2[6];
#pragma unroll
        for (int kt = 0; kt < 6; ++kt) {
            const int cb = kt * 16 + tig * 2;
            afr0[kt] = *(const uint32*)&sh[buf][gid][cb];
            afr2[kt] = *(const uint32*)&sh[buf][gid][cb + 8];
        }

        // tensor matvec: [h,x] @ Wcomb^T, warp's 4 n-tiles (one per gate)
        float cfr[4][4];
#pragma unroll
        for (int gi = 0; gi < 4; ++gi) {
            cfr[gi][0] = 0.f; cfr[gi][1] = 0.f; cfr[gi][2] = 0.f; cfr[gi][3] = 0.f;
#pragma unroll
            for (int kt = 0; kt < 6; ++kt)
                mma16816(cfr[gi], afr0[kt], 0u, afr2[kt], 0u,
                         bfr[gi][kt][0], bfr[gi][kt][1]);
        }

        // stage x(t+1) into other buffer
        if (pf) sh[buf ^ 1][prow][64 + pd] = __float2half(xv);

        // local activation + cell update (all four gates in-register)
        float vi0 = cfr[0][0] + bia[0][0], vi1 = cfr[0][1] + bia[0][1];
        float vf0 = cfr[1][0] + bia[1][0], vf1 = cfr[1][1] + bia[1][1];
        float vg0 = cfr[2][0] + bia[2][0], vg1 = cfr[2][1] + bia[2][1];
        float vo0 = cfr[3][0] + bia[3][0], vo1 = cfr[3][1] + bia[3][1];

        float i0 = sigm(vi0), f0 = sigm(vf0), g0 = tanh_(vg0), o0 = sigm(vo0);
        float i1 = sigm(vi1), f1 = sigm(vf1), g1 = tanh_(vg1), o1 = sigm(vo1);
        cc0 = fmaf(f0, cc0, i0 * g0);
        cc1 = fmaf(f1, cc1, i1 * g1);
        float hv0 = o0 * tanh_(cc0);
        float hv1 = o1 * tanh_(cc1);

        // h(t+1) -> other buffer (units adjacent: one half2 store)
        *(__half2*)&sh[buf ^ 1][gid][wid * 8 + tig * 2] =
            __floats2half2_rn(hv0, hv1);

        // logit partial for row gid (this warp's 8 units), parity-buffered
        float p = hv0 * wl0 + hv1 * wl1;
        p += __shfl_down_sync(0xffffffffu, p, 1, 4);
        p += __shfl_down_sync(0xffffffffu, p, 2, 4);
        if (tig == 0) s_part[buf][gid][wid] = p;

        // combine previous step's logit partials (8 threads, other parity)
        if (t > 0 && tid < RPB) {
            float a = blv;
#pragma unroll
            for (int w = 0; w < 8; ++w) a += s_part[buf ^ 1][tid][w];
            s_log[tid * Nseq + (t - 1)] = a;
        }

        __syncthreads();   // ONE barrier: buf^1 (h,x) + s_part[buf] ready
    }

    if (tid < RPB) {
        float a = blv;
#pragma unroll
        for (int w = 0; w < 8; ++w) a += s_part[(Nseq - 1) & 1][tid][w];
        s_log[tid * Nseq + (Nseq - 1)] = a;
    }
    __syncthreads();

    // ---- softmax over t: warp r handles row r ----
    {
        float v[16];
#pragma unroll
        for (int i = 0; i < 16; ++i)
            v[i] = s_log[wid * Nseq + i * 32 + lane];
        float m = v[0];
#pragma unroll
        for (int i = 1; i < 16; ++i) m = fmaxf(m, v[i]);
#pragma unroll
        for (int off = 16; off >= 1; off >>= 1)
            m = fmaxf(m, __shfl_xor_sync(0xffffffffu, m, off));

        float e[16], sum = 0.0f;
#pragma unroll
        for (int i = 0; i < 16; ++i) {
            e[i] = ex2a((v[i] - m) * 1.4426950408889634f);
            sum += e[i];
        }
#pragma unroll
        for (int off = 16; off >= 1; off >>= 1)
            sum += __shfl_xor_sync(0xffffffffu, sum, off);
        const float inv = 1.0f / sum;

        float* orow = out + (size_t)(b0 + wid) * Nseq;
#pragma unroll
        for (int i = 0; i < 16; ++i)
            orow[i * 32 + lane] = e[i] * inv;
    }
}

// ---------------------------------------------------------------------------
extern "C" void kernel_launch(void* const* d_in, const int* in_sizes, int n_in,
                              void* d_out, int out_size) {
    const float* x     = (const float*)d_in[0];
    const float* Wfc   = (const float*)d_in[1];
    const float* bfc   = (const float*)d_in[2];
    const float* Wih   = (const float*)d_in[3];
    const float* Whh   = (const float*)d_in[4];
    const float* bih   = (const float*)d_in[5];
    const float* bhh   = (const float*)d_in[6];
    const float* Wlast = (const float*)d_in[7];
    const float* blast = (const float*)d_in[8];
    float* out = (float*)d_out;

    prep_kernel<<<256, 32>>>(Wfc, bfc, Wih, Whh, bih, bhh);
    lstm_kernel<<<NBLK, 256>>>(x, Wlast, blast, out);
}